// round 12
// baseline (speedup 1.0000x reference)
#include <cuda_runtime.h>
#include <math.h>

#define JJN  20
#define NH   16
#define NSEQ 8192
#define NB   8
#define HD4  16          // float4 per 64-float row
#define GROUPS 32        // 256 threads / 8 lanes
#define POS_PER_CTA 128  // GROUPS * 4
#define EPOS 24
#define EGRP 100
#define NROW 47
#define NSLOT 80
#define RING 4

// Consumer-side tables (divergent lane-indexed LDC at reduce events).
// c_A[i] = c_P[i]*EPOS + c_J[i] (precombined -> single LDC per event).
__constant__ int c_T[NSLOT] = {
    -1024,-1023,-1022,-1021,-512,-511,-510,-509,-256,-255,-254,-253,
    -128,-127,-126,-125,-64,-63,-62,-61,-32,-31,-30,-29,-23,-22,-21,-20,-16,
    -15,-15,-14,-14,-13,-13,-13,-12,-12,-11,-11,-10,-10,-9,-9,-8,-8,-8,-7,-7,-7,
    -6,-6,-6,-6,-5,-5,-5,-5,-4,-4,-4,-4,-3,-3,-3,-3,-2,-2,-2,-2,-1,-1,-1,-1,
    0,0,0,1,1,2 };
__constant__ int c_A[NSLOT] = {
    19,43,67,91, 18,42,66,90, 17,41,65,89, 16,40,64,88, 15,39,63,87,
    14,38,62,86, 13,37,61,85, 12,
    11,36, 35,60, 10,59,84, 34,83, 9,58, 33,82, 8,57, 7,32,81, 6,31,56,
    5,30,55,80, 4,29,54,79, 3,28,53,78, 2,27,52,77, 1,26,51,76, 0,25,50,75,
    24,49,74, 48,73, 72 };

// ---- packed f32x2 helpers ----
struct f2 { unsigned long long u; };
__device__ __forceinline__ f2 fpack(float x, float y) {
    f2 r; asm("mov.b64 %0, {%1,%2};" : "=l"(r.u) : "f"(x), "f"(y)); return r;
}
__device__ __forceinline__ f2 ffma2(f2 a, f2 b, f2 c) {
    f2 r; asm("fma.rn.f32x2 %0, %1, %2, %3;" : "=l"(r.u) : "l"(a.u), "l"(b.u), "l"(c.u)); return r;
}
__device__ __forceinline__ f2 fmul2(f2 a, f2 b) {
    f2 r; asm("mul.rn.f32x2 %0, %1, %2;" : "=l"(r.u) : "l"(a.u), "l"(b.u)); return r;
}
__device__ __forceinline__ void funpack(f2 a, float& x, float& y) {
    asm("mov.b64 {%0,%1}, %2;" : "=f"(x), "=f"(y) : "l"(a.u));
}
__device__ __forceinline__ float ex2f(float x) {
    float r; asm("ex2.approx.f32 %0, %1;" : "=f"(r) : "f"(x)); return r;
}

// 8-lane x 8-partial butterfly reduce-scatter: lane l gets full sum of slot l.
__device__ __forceinline__ float rscatter8(float part[8], int lane8) {
    {
        const bool hi = (lane8 & 4) != 0;
        #pragma unroll
        for (int i = 0; i < 4; i++) {
            float keep = hi ? part[i + 4] : part[i];
            float send = hi ? part[i]     : part[i + 4];
            part[i] = keep + __shfl_xor_sync(0xffffffffu, send, 4);
        }
    }
    {
        const bool hi = (lane8 & 2) != 0;
        #pragma unroll
        for (int i = 0; i < 2; i++) {
            float keep = hi ? part[i + 2] : part[i];
            float send = hi ? part[i]     : part[i + 2];
            part[i] = keep + __shfl_xor_sync(0xffffffffu, send, 2);
        }
    }
    {
        const bool hi = (lane8 & 1) != 0;
        float keep = hi ? part[1] : part[0];
        float send = hi ? part[0] : part[1];
        return keep + __shfl_xor_sync(0xffffffffu, send, 1);
    }
}

// Streaming phases, templated on whether row-index clamping/masking is needed.
// CLAMP==false (seq0 >= 1024): rc = n0 + t exactly -> ptxas folds t*256 into
// LDG immediates off one base register; all validity masks vanish.
template<bool CLAMP>
__device__ __forceinline__ void run_main(
    const int n0, const int lane8, const int egbase,
    const float4* __restrict__ kb4, const float4* __restrict__ vb4,
    const f2 (&qv)[4][4], float* __restrict__ s_e,
    float4* __restrict__ ob4)
{
    const int ROW_T[NROW] = {
        -1024,-1023,-1022,-1021, -512,-511,-510,-509, -256,-255,-254,-253,
        -128,-127,-126,-125, -64,-63,-62,-61, -32,-31,-30,-29, -23,-22,-21,-20,
        -16,-15,-14,-13,-12,-11,-10,-9,-8,-7,-6,-5,-4,-3,-2,-1,0,1,2 };
    const int SLOT_ROW[NSLOT] = {
        0,1,2,3,4,5,6,7,8,9,10,11,12,13,14,15,16,17,18,19,20,21,22,23,24,25,26,27,28,
        29,29, 30,30, 31,31,31, 32,32, 33,33, 34,34, 35,35, 36,36,36, 37,37,37,
        38,38,38,38, 39,39,39,39, 40,40,40,40, 41,41,41,41, 42,42,42,42, 43,43,43,43,
        44,44,44, 45,45, 46 };
    const int SLOT_P[NSLOT] = {
        0,1,2,3, 0,1,2,3, 0,1,2,3, 0,1,2,3, 0,1,2,3, 0,1,2,3, 0,1,2,3, 0,
        0,1, 1,2, 0,2,3, 1,3, 0,2, 1,3, 0,2, 0,1,3, 0,1,2,
        0,1,2,3, 0,1,2,3, 0,1,2,3, 0,1,2,3, 0,1,2,3, 0,1,2,3,
        1,2,3, 2,3, 3 };
    const int SLOT_J[NSLOT] = {
        19,19,19,19, 18,18,18,18, 17,17,17,17, 16,16,16,16, 15,15,15,15,
        14,14,14,14, 13,13,13,13, 12,
        11,12, 11,12, 10,11,12, 10,11, 9,10, 9,10, 8,9, 7,8,9, 6,7,8,
        5,6,7,8, 4,5,6,7, 3,4,5,6, 2,3,4,5, 1,2,3,4, 0,1,2,3,
        0,1,2, 0,1, 0 };

    float part[8];

    // ========== PHASE 1: scores -> e (far-first rows, ring-4 prefetch) ==========
    {
        f2 kbuf[RING][4];
        #pragma unroll
        for (int r = 0; r < RING; r++) {
            int rr = n0 + ROW_T[r];
            int rc = CLAMP ? ((rr < 0) ? 0 : rr) : rr;
            const float4* kr = kb4 + (size_t)rc * HD4;
            float4 a = kr[lane8], b = kr[lane8 + 8];
            kbuf[r][0] = fpack(a.x, a.y); kbuf[r][1] = fpack(a.z, a.w);
            kbuf[r][2] = fpack(b.x, b.y); kbuf[r][3] = fpack(b.z, b.w);
        }

        #pragma unroll
        for (int i = 0; i < NSLOT; i++) {
            const int r  = SLOT_ROW[i];
            const int bi = r % RING;
            const int p  = SLOT_P[i];

            f2 a = fmul2(qv[p][0], kbuf[bi][0]);
            a = ffma2(qv[p][1], kbuf[bi][1], a);
            a = ffma2(qv[p][2], kbuf[bi][2], a);
            a = ffma2(qv[p][3], kbuf[bi][3], a);
            float x, y; funpack(a, x, y);
            part[i & 7] = x + y;

            // last slot of this row -> refill buffer with row r+RING
            if (((i == NSLOT - 1) || (SLOT_ROW[i + 1] != r)) && (r + RING) < NROW) {
                int rr = n0 + ROW_T[r + RING];
                int rc = CLAMP ? ((rr < 0) ? 0 : rr) : rr;
                const float4* kr = kb4 + (size_t)rc * HD4;
                float4 fa = kr[lane8], fb = kr[lane8 + 8];
                kbuf[bi][0] = fpack(fa.x, fa.y); kbuf[bi][1] = fpack(fa.z, fa.w);
                kbuf[bi][2] = fpack(fb.x, fb.y); kbuf[bi][3] = fpack(fb.z, fb.w);
            }

            if ((i & 7) == 7) {
                float red = rscatter8(part, lane8);
                const int base = i - 7;
                const int addr = egbase + c_A[base + lane8];
                // No max-subtraction: scores are O(+-8), far below exp2 range.
                float e = ex2f(red + s_e[addr]);
                if (CLAMP) {
                    const float validf = (n0 + c_T[base + lane8] >= 0) ? 1.0f : 0.0f;
                    e *= validf;
                }
                s_e[addr] = e;
            }
        }
    }
    __syncwarp();

    // ========== denominators ==========
    if (lane8 < 4) {
        const float4* ep = (const float4*)&s_e[egbase + lane8 * EPOS];
        float4 a = ep[0], b = ep[1], c = ep[2], d = ep[3], e4 = ep[4];
        float s = a.x + a.y + a.z + a.w + b.x + b.y + b.z + b.w
                + c.x + c.y + c.z + c.w + d.x + d.y + d.z + d.w
                + e4.x + e4.y + e4.z + e4.w;
        s_e[egbase + lane8 * EPOS + 20] = 1.0f / fmaxf(s, 1e-30f);
    }
    __syncwarp();

    // ========== PHASE 2: out = (sum_j e * v) * inv (same ring streaming) ==========
    {
        f2 oacc[4][4];
        #pragma unroll
        for (int p = 0; p < 4; p++)
            #pragma unroll
            for (int c = 0; c < 4; c++) oacc[p][c] = fpack(0.f, 0.f);

        f2 vbuf[RING][4];
        #pragma unroll
        for (int r = 0; r < RING; r++) {
            int rr = n0 + ROW_T[r];
            int rc = CLAMP ? ((rr < 0) ? 0 : rr) : rr;   // e==0 when masked
            const float4* vr = vb4 + (size_t)rc * HD4;
            float4 a = vr[lane8], b = vr[lane8 + 8];
            vbuf[r][0] = fpack(a.x, a.y); vbuf[r][1] = fpack(a.z, a.w);
            vbuf[r][2] = fpack(b.x, b.y); vbuf[r][3] = fpack(b.z, b.w);
        }

        #pragma unroll
        for (int i = 0; i < NSLOT; i++) {
            const int r  = SLOT_ROW[i];
            const int bi = r % RING;
            const int p  = SLOT_P[i];

            const float e = s_e[egbase + p * EPOS + SLOT_J[i]];
            f2 e2 = fpack(e, e);
            oacc[p][0] = ffma2(e2, vbuf[bi][0], oacc[p][0]);
            oacc[p][1] = ffma2(e2, vbuf[bi][1], oacc[p][1]);
            oacc[p][2] = ffma2(e2, vbuf[bi][2], oacc[p][2]);
            oacc[p][3] = ffma2(e2, vbuf[bi][3], oacc[p][3]);

            if (((i == NSLOT - 1) || (SLOT_ROW[i + 1] != r)) && (r + RING) < NROW) {
                int rr = n0 + ROW_T[r + RING];
                int rc = CLAMP ? ((rr < 0) ? 0 : rr) : rr;
                const float4* vr = vb4 + (size_t)rc * HD4;
                float4 fa = vr[lane8], fb = vr[lane8 + 8];
                vbuf[bi][0] = fpack(fa.x, fa.y); vbuf[bi][1] = fpack(fa.z, fa.w);
                vbuf[bi][2] = fpack(fb.x, fb.y); vbuf[bi][3] = fpack(fb.z, fb.w);
            }
        }

        #pragma unroll
        for (int p = 0; p < 4; p++) {
            const float inv = s_e[egbase + p * EPOS + 20];
            f2 iv = fpack(inv, inv);
            f2 r0 = fmul2(oacc[p][0], iv);
            f2 r1 = fmul2(oacc[p][1], iv);
            f2 r2 = fmul2(oacc[p][2], iv);
            f2 r3 = fmul2(oacc[p][3], iv);
            float4 oA, oB;
            funpack(r0, oA.x, oA.y); funpack(r1, oA.z, oA.w);
            funpack(r2, oB.x, oB.y); funpack(r3, oB.z, oB.w);
            float4* o4 = ob4 + (size_t)(n0 + p) * HD4;
            o4[lane8]     = oA;
            o4[lane8 + 8] = oB;
        }
    }
}

__global__ __launch_bounds__(256, 3)
void dsqg_attn_kernel(const float* __restrict__ q,
                      const float* __restrict__ k,
                      const float* __restrict__ v,
                      const float* __restrict__ pos_bias,     // [J, H]
                      const float* __restrict__ scale_embed,  // [J, HD]
                      float* __restrict__ out)
{
    __shared__ float4 s_se[JJN][HD4];     // 5 KB
    __shared__ float  s_pb[JJN];
    __shared__ float  s_e[GROUPS * EGRP]; // 12.8 KB

    const int blocks_per_seq = NSEQ / POS_PER_CTA;          // 64
    const int bh   = blockIdx.x / blocks_per_seq;
    const int seq0 = (blockIdx.x % blocks_per_seq) * POS_PER_CTA;
    const int h    = bh % NH;

    const float LOG2E = 1.4426950408889634f;
    for (int i = threadIdx.x; i < JJN * HD4; i += 256)
        ((float4*)s_se)[i] = ((const float4*)scale_embed)[i];
    if (threadIdx.x < JJN)
        s_pb[threadIdx.x] = pos_bias[threadIdx.x * NH + h] * LOG2E;
    __syncthreads();

    const int gid   = threadIdx.x >> 3;
    const int lane8 = threadIdx.x & 7;
    const int n0    = seq0 + gid * 4;
    const int egbase = gid * EGRP;

    const size_t bh_row0 = (size_t)bh * NSEQ * HD4;
    const float4* __restrict__ kb4 = (const float4*)k + bh_row0;
    const float4* __restrict__ vb4 = (const float4*)v + bh_row0;
    const float4* __restrict__ qb4 = (const float4*)q + bh_row0;
    float4* __restrict__ ob4 = (float4*)out + bh_row0;

    // q pre-scaled by (1/sqrt(64))*log2(e) so e = ex2(dot + qse_term)
    const float qs = 0.125f * LOG2E;
    f2 qv[4][4];
    #pragma unroll
    for (int p = 0; p < 4; p++) {
        const float4* qr = qb4 + (size_t)(n0 + p) * HD4;
        float4 a = qr[lane8], b = qr[lane8 + 8];
        qv[p][0] = fpack(a.x * qs, a.y * qs);
        qv[p][1] = fpack(a.z * qs, a.w * qs);
        qv[p][2] = fpack(b.x * qs, b.y * qs);
        qv[p][3] = fpack(b.z * qs, b.w * qs);
    }

    // ========== PHASE 0: qse[p][j] = q.se_j (scaled) + pb_j -> s_e ==========
    {
        float part[8];
        f2 s0, s1, s2, s3;
        #pragma unroll
        for (int i = 0; i < 80; i++) {
            const int j = i >> 2;
            if ((i & 3) == 0) {
                float4 sa = s_se[j][lane8], sb = s_se[j][lane8 + 8];
                s0 = fpack(sa.x, sa.y); s1 = fpack(sa.z, sa.w);
                s2 = fpack(sb.x, sb.y); s3 = fpack(sb.z, sb.w);
            }
            const int p = i & 3;
            f2 a = fmul2(qv[p][0], s0);
            a = ffma2(qv[p][1], s1, a);
            a = ffma2(qv[p][2], s2, a);
            a = ffma2(qv[p][3], s3, a);
            float x, y; funpack(a, x, y);
            part[i & 7] = x + y;
            if ((i & 7) == 7) {
                float red = rscatter8(part, lane8);
                const int pp = lane8 & 3;
                const int jj = 2 * (i >> 3) + (lane8 >> 2);
                s_e[egbase + pp * EPOS + jj] = red + s_pb[jj];
            }
        }
    }
    __syncwarp();

    // 7/8 of CTAs need no clamping or masking at all (CTA-uniform branch).
    if (seq0 >= 1024) {
        run_main<false>(n0, lane8, egbase, kb4, vb4, qv, s_e, ob4);
    } else {
        run_main<true>(n0, lane8, egbase, kb4, vb4, qv, s_e, ob4);
    }
}

extern "C" void kernel_launch(void* const* d_in, const int* in_sizes, int n_in,
                              void* d_out, int out_size)
{
    const float* q  = (const float*)d_in[0];
    const float* k  = (const float*)d_in[1];
    const float* v  = (const float*)d_in[2];
    const float* pb = (const float*)d_in[3];
    const float* se = (const float*)d_in[4];
    float* out = (float*)d_out;

    const int blocks = NB * NH * (NSEQ / POS_PER_CTA);   // 8192
    dsqg_attn_kernel<<<blocks, 256>>>(q, k, v, pb, se, out);
}

// round 13
// speedup vs baseline: 1.0473x; 1.0473x over previous
#include <cuda_runtime.h>
#include <math.h>

#define JJN  20
#define NH   16
#define NSEQ 8192
#define NB   8
#define HD4  16          // float4 per 64-float row
#define GROUPS 32        // 256 threads / 8 lanes
#define POS_PER_CTA 128  // GROUPS * 4
#define EPOS 24
#define EGRP 100
#define NSLOT 80
#define NFAR 28
#define NDENSE 19
#define RINGF 6
#define RINGD 3

// Consumer-side tables in WOVEN slot order (divergent lane-indexed LDC at
// reduce events). c_A = p*EPOS + j precombined.
__constant__ int c_T[NSLOT] = {
    -1024,-1023,-16,-1022,-1021,-15,-15,-512,-511,-14,-14,-510,-509,-13,-13,-13,
    -256,-255,-12,-12,-254,-253,-11,-11,-128,-127,-10,-10,-126,-125,-9,-9,
    -64,-63,-8,-8,-8,-62,-7,-7,-7,-61,-6,-6,-6,-6,-32,-5,-5,-5,-5,-31,
    -4,-4,-4,-4,-30,-3,-3,-3,-3,-29,-2,-2,-2,-2,-23,-1,-1,-1,-1,-22,
    0,0,0,-21,1,1,-20,2 };
__constant__ int c_A[NSLOT] = {
    19,43,12,67,91,11,36,18,42,35,60,66,90,10,59,84,
    17,41,34,83,65,89,9,58,16,40,33,82,64,88,8,57,
    15,39,7,32,81,63,6,31,56,87,5,30,55,80,14,4,29,54,79,38,
    3,28,53,78,62,2,27,52,77,86,1,26,51,76,13,0,25,50,75,37,
    24,49,74,61,48,73,85,72 };

// ---- packed f32x2 helpers ----
struct f2 { unsigned long long u; };
__device__ __forceinline__ f2 fpack(float x, float y) {
    f2 r; asm("mov.b64 %0, {%1,%2};" : "=l"(r.u) : "f"(x), "f"(y)); return r;
}
__device__ __forceinline__ f2 ffma2(f2 a, f2 b, f2 c) {
    f2 r; asm("fma.rn.f32x2 %0, %1, %2, %3;" : "=l"(r.u) : "l"(a.u), "l"(b.u), "l"(c.u)); return r;
}
__device__ __forceinline__ f2 fmul2(f2 a, f2 b) {
    f2 r; asm("mul.rn.f32x2 %0, %1, %2;" : "=l"(r.u) : "l"(a.u), "l"(b.u)); return r;
}
__device__ __forceinline__ void funpack(f2 a, float& x, float& y) {
    asm("mov.b64 {%0,%1}, %2;" : "=f"(x), "=f"(y) : "l"(a.u));
}
__device__ __forceinline__ float ex2f(float x) {
    float r; asm("ex2.approx.f32 %0, %1;" : "=f"(r) : "f"(x)); return r;
}

// 8-lane x 8-partial butterfly reduce-scatter: lane l gets full sum of slot l.
__device__ __forceinline__ float rscatter8(float part[8], int lane8) {
    {
        const bool hi = (lane8 & 4) != 0;
        #pragma unroll
        for (int i = 0; i < 4; i++) {
            float keep = hi ? part[i + 4] : part[i];
            float send = hi ? part[i]     : part[i + 4];
            part[i] = keep + __shfl_xor_sync(0xffffffffu, send, 4);
        }
    }
    {
        const bool hi = (lane8 & 2) != 0;
        #pragma unroll
        for (int i = 0; i < 2; i++) {
            float keep = hi ? part[i + 2] : part[i];
            float send = hi ? part[i]     : part[i + 2];
            part[i] = keep + __shfl_xor_sync(0xffffffffu, send, 2);
        }
    }
    {
        const bool hi = (lane8 & 1) != 0;
        float keep = hi ? part[1] : part[0];
        float send = hi ? part[0] : part[1];
        return keep + __shfl_xor_sync(0xffffffffu, send, 1);
    }
}

// Woven schedule, compile-time only (fully unrolled everywhere indexed).
#define SCHED_TABLES                                                         \
    const int IS_FAR[NSLOT] = {                                              \
        1,1,0,1,1,0,0,1,1,0,0,1,1,0,0,0,1,1,0,0,1,1,0,0,1,1,0,0,1,1,0,0,    \
        1,1,0,0,0,1,0,0,0,1,0,0,0,0,1,0,0,0,0,1,0,0,0,0,1,0,0,0,0,1,0,0,    \
        0,0,1,0,0,0,0,1,0,0,0,1,0,0,1,0 };                                   \
    const int FAR_IDX[NSLOT] = {                                             \
        0,1,-1,2,3,-1,-1,4,5,-1,-1,6,7,-1,-1,-1,8,9,-1,-1,10,11,-1,-1,       \
        12,13,-1,-1,14,15,-1,-1,16,17,-1,-1,-1,18,-1,-1,-1,19,-1,-1,-1,-1,   \
        20,-1,-1,-1,-1,21,-1,-1,-1,-1,22,-1,-1,-1,-1,23,-1,-1,-1,-1,24,      \
        -1,-1,-1,-1,25,-1,-1,-1,26,-1,-1,27,-1 };                            \
    const int FAR_T[NFAR] = {                                                \
        -1024,-1023,-1022,-1021,-512,-511,-510,-509,-256,-255,-254,-253,     \
        -128,-127,-126,-125,-64,-63,-62,-61,-32,-31,-30,-29,-23,-22,-21,-20 };\
    const int DROW[NSLOT] = {                                                \
        -1,-1,0,-1,-1,1,1,-1,-1,2,2,-1,-1,3,3,3,-1,-1,4,4,-1,-1,5,5,         \
        -1,-1,6,6,-1,-1,7,7,-1,-1,8,8,8,-1,9,9,9,-1,10,10,10,10,-1,          \
        11,11,11,11,-1,12,12,12,12,-1,13,13,13,13,-1,14,14,14,14,-1,         \
        15,15,15,15,-1,16,16,16,-1,17,17,-1,18 };                            \
    const int DLAST[NSLOT] = {                                               \
        0,0,1,0,0,0,1,0,0,0,1,0,0,0,0,1,0,0,0,1,0,0,0,1,0,0,0,1,0,0,0,1,    \
        0,0,0,0,1,0,0,0,1,0,0,0,0,1,0,0,0,0,1,0,0,0,0,1,0,0,0,0,1,0,0,0,    \
        0,1,0,0,0,0,1,0,0,0,1,0,0,1,0,1 };                                   \
    const int SLOT_P[NSLOT] = {                                              \
        0,1,0,2,3,0,1,0,1,1,2,2,3,0,2,3,0,1,1,3,2,3,0,2,0,1,1,3,2,3,0,2,    \
        0,1,0,1,3,2,0,1,2,3,0,1,2,3,0,0,1,2,3,1,0,1,2,3,2,0,1,2,3,3,0,1,    \
        2,3,0,0,1,2,3,1,1,2,3,2,2,3,3,3 };                                   \
    const int SLOT_J[NSLOT] = {                                              \
        19,19,12,19,19,11,12,18,18,11,12,18,18,10,11,12,17,17,10,11,17,17,   \
        9,10,16,16,9,10,16,16,8,9,15,15,7,8,9,15,6,7,8,15,5,6,7,8,14,        \
        4,5,6,7,14,3,4,5,6,14,2,3,4,5,14,1,2,3,4,13,0,1,2,3,13,              \
        0,1,2,13,0,1,13,0 };

// Load one 256B row (k or v) into 4 f2 registers (lane covers slots lane8, lane8+8).
#define LOAD_ROW(dst, basep, rc)                                             \
    do {                                                                     \
        const float4* _r = (basep) + (size_t)(rc) * HD4;                     \
        float4 _a = _r[lane8], _b = _r[lane8 + 8];                           \
        (dst)[0] = fpack(_a.x, _a.y); (dst)[1] = fpack(_a.z, _a.w);          \
        (dst)[2] = fpack(_b.x, _b.y); (dst)[3] = fpack(_b.z, _b.w);          \
    } while (0)

template<bool CLAMP>
__device__ __forceinline__ int rowclamp(int rr) {
    return CLAMP ? ((rr < 0) ? 0 : rr) : rr;
}

// Streaming phases with the woven far/dense schedule.
// kf: far ring preloaded by caller (rows F0..F5) so phase 0 covered its latency.
template<bool CLAMP>
__device__ __forceinline__ void run_main(
    const int n0, const int lane8, const int egbase,
    const float4* __restrict__ kb4, const float4* __restrict__ vb4,
    const f2 (&qv)[4][4], f2 (&kf)[RINGF][4], float* __restrict__ s_e,
    float4* __restrict__ ob4)
{
    SCHED_TABLES
    float part[8];

    // ========== PHASE 1: scores -> e ==========
    {
        f2 kd[RINGD][4];
        #pragma unroll
        for (int r = 0; r < RINGD; r++)
            LOAD_ROW(kd[r], kb4, rowclamp<CLAMP>(n0 - 16 + r));

        #pragma unroll
        for (int i = 0; i < NSLOT; i++) {
            const int p = SLOT_P[i];
            f2 a;
            if (IS_FAR[i]) {
                const int fi = FAR_IDX[i];
                const int bi = fi % RINGF;
                a = fmul2(qv[p][0], kf[bi][0]);
                a = ffma2(qv[p][1], kf[bi][1], a);
                a = ffma2(qv[p][2], kf[bi][2], a);
                a = ffma2(qv[p][3], kf[bi][3], a);
                if (fi + RINGF < NFAR)   // refill far ring (used ~20 slots later)
                    LOAD_ROW(kf[bi], kb4, rowclamp<CLAMP>(n0 + FAR_T[fi + RINGF]));
            } else {
                const int dr = DROW[i];
                const int bd = dr % RINGD;
                a = fmul2(qv[p][0], kd[bd][0]);
                a = ffma2(qv[p][1], kd[bd][1], a);
                a = ffma2(qv[p][2], kd[bd][2], a);
                a = ffma2(qv[p][3], kd[bd][3], a);
                if (DLAST[i] && (dr + RINGD) < NDENSE)
                    LOAD_ROW(kd[bd], kb4, rowclamp<CLAMP>(n0 - 16 + dr + RINGD));
            }
            float x, y; funpack(a, x, y);
            part[i & 7] = x + y;

            if ((i & 7) == 7) {
                float red = rscatter8(part, lane8);
                const int base = i - 7;
                const int addr = egbase + c_A[base + lane8];
                // No max-subtraction: scores are O(+-8), far below exp2 range.
                float e = ex2f(red + s_e[addr]);
                if (CLAMP) {
                    const float validf = (n0 + c_T[base + lane8] >= 0) ? 1.0f : 0.0f;
                    e *= validf;
                }
                s_e[addr] = e;
            }
        }
    }
    __syncwarp();

    // Preload far v ring NOW so the denominator block covers its latency.
    f2 vf[RINGF][4];
    #pragma unroll
    for (int r = 0; r < RINGF; r++) {
        SCHED_TABLES
        LOAD_ROW(vf[r], vb4, rowclamp<CLAMP>(n0 + FAR_T[r]));
    }

    // ========== denominators ==========
    if (lane8 < 4) {
        const float4* ep = (const float4*)&s_e[egbase + lane8 * EPOS];
        float4 a = ep[0], b = ep[1], c = ep[2], d = ep[3], e4 = ep[4];
        float s = a.x + a.y + a.z + a.w + b.x + b.y + b.z + b.w
                + c.x + c.y + c.z + c.w + d.x + d.y + d.z + d.w
                + e4.x + e4.y + e4.z + e4.w;
        s_e[egbase + lane8 * EPOS + 20] = 1.0f / fmaxf(s, 1e-30f);
    }
    __syncwarp();

    // ========== PHASE 2: out = (sum_j e * v) * inv ==========
    {
        SCHED_TABLES
        f2 oacc[4][4];
        #pragma unroll
        for (int p = 0; p < 4; p++)
            #pragma unroll
            for (int c = 0; c < 4; c++) oacc[p][c] = fpack(0.f, 0.f);

        f2 vd[RINGD][4];
        #pragma unroll
        for (int r = 0; r < RINGD; r++)
            LOAD_ROW(vd[r], vb4, rowclamp<CLAMP>(n0 - 16 + r));

        #pragma unroll
        for (int i = 0; i < NSLOT; i++) {
            const int p = SLOT_P[i];
            const float e = s_e[egbase + p * EPOS + SLOT_J[i]];  // e==0 when masked
            f2 e2 = fpack(e, e);
            if (IS_FAR[i]) {
                const int fi = FAR_IDX[i];
                const int bi = fi % RINGF;
                oacc[p][0] = ffma2(e2, vf[bi][0], oacc[p][0]);
                oacc[p][1] = ffma2(e2, vf[bi][1], oacc[p][1]);
                oacc[p][2] = ffma2(e2, vf[bi][2], oacc[p][2]);
                oacc[p][3] = ffma2(e2, vf[bi][3], oacc[p][3]);
                if (fi + RINGF < NFAR)
                    LOAD_ROW(vf[bi], vb4, rowclamp<CLAMP>(n0 + FAR_T[fi + RINGF]));
            } else {
                const int dr = DROW[i];
                const int bd = dr % RINGD;
                oacc[p][0] = ffma2(e2, vd[bd][0], oacc[p][0]);
                oacc[p][1] = ffma2(e2, vd[bd][1], oacc[p][1]);
                oacc[p][2] = ffma2(e2, vd[bd][2], oacc[p][2]);
                oacc[p][3] = ffma2(e2, vd[bd][3], oacc[p][3]);
                if (DLAST[i] && (dr + RINGD) < NDENSE)
                    LOAD_ROW(vd[bd], vb4, rowclamp<CLAMP>(n0 - 16 + dr + RINGD));
            }
        }

        #pragma unroll
        for (int p = 0; p < 4; p++) {
            const float inv = s_e[egbase + p * EPOS + 20];
            f2 iv = fpack(inv, inv);
            f2 r0 = fmul2(oacc[p][0], iv);
            f2 r1 = fmul2(oacc[p][1], iv);
            f2 r2 = fmul2(oacc[p][2], iv);
            f2 r3 = fmul2(oacc[p][3], iv);
            float4 oA, oB;
            funpack(r0, oA.x, oA.y); funpack(r1, oA.z, oA.w);
            funpack(r2, oB.x, oB.y); funpack(r3, oB.z, oB.w);
            float4* o4 = ob4 + (size_t)(n0 + p) * HD4;
            o4[lane8]     = oA;
            o4[lane8 + 8] = oB;
        }
    }
}

__global__ __launch_bounds__(256, 2)
void dsqg_attn_kernel(const float* __restrict__ q,
                      const float* __restrict__ k,
                      const float* __restrict__ v,
                      const float* __restrict__ pos_bias,     // [J, H]
                      const float* __restrict__ scale_embed,  // [J, HD]
                      float* __restrict__ out)
{
    __shared__ float4 s_se[JJN][HD4];     // 5 KB
    __shared__ float  s_pb[JJN];
    __shared__ float  s_e[GROUPS * EGRP]; // 12.8 KB

    const int blocks_per_seq = NSEQ / POS_PER_CTA;          // 64
    const int bh   = blockIdx.x / blocks_per_seq;
    const int seq0 = (blockIdx.x % blocks_per_seq) * POS_PER_CTA;
    const int h    = bh % NH;

    const float LOG2E = 1.4426950408889634f;
    for (int i = threadIdx.x; i < JJN * HD4; i += 256)
        ((float4*)s_se)[i] = ((const float4*)scale_embed)[i];
    if (threadIdx.x < JJN)
        s_pb[threadIdx.x] = pos_bias[threadIdx.x * NH + h] * LOG2E;
    __syncthreads();

    const int gid   = threadIdx.x >> 3;
    const int lane8 = threadIdx.x & 7;
    const int n0    = seq0 + gid * 4;
    const int egbase = gid * EGRP;

    const size_t bh_row0 = (size_t)bh * NSEQ * HD4;
    const float4* __restrict__ kb4 = (const float4*)k + bh_row0;
    const float4* __restrict__ vb4 = (const float4*)v + bh_row0;
    const float4* __restrict__ qb4 = (const float4*)q + bh_row0;
    float4* __restrict__ ob4 = (float4*)out + bh_row0;

    const bool clamp = (seq0 < 1024);

    // q pre-scaled by (1/sqrt(64))*log2(e) so e = ex2(dot + qse_term)
    const float qs = 0.125f * LOG2E;
    f2 qv[4][4];
    #pragma unroll
    for (int p = 0; p < 4; p++) {
        const float4* qr = qb4 + (size_t)(n0 + p) * HD4;
        float4 a = qr[lane8], b = qr[lane8 + 8];
        qv[p][0] = fpack(a.x * qs, a.y * qs);
        qv[p][1] = fpack(a.z * qs, a.w * qs);
        qv[p][2] = fpack(b.x * qs, b.y * qs);
        qv[p][3] = fpack(b.z * qs, b.w * qs);
    }

    // Preload the far k ring BEFORE phase 0 — phase 0's ~700 cycles of pure
    // FMA/shfl work fully covers these 6 L2-distance loads.
    f2 kf[RINGF][4];
    {
        SCHED_TABLES
        #pragma unroll
        for (int r = 0; r < RINGF; r++) {
            int rr = n0 + FAR_T[r];
            int rc = clamp ? ((rr < 0) ? 0 : rr) : rr;
            LOAD_ROW(kf[r], kb4, rc);
        }
    }

    // ========== PHASE 0: qse[p][j] = q.se_j (scaled) + pb_j -> s_e ==========
    {
        float part[8];
        f2 s0, s1, s2, s3;
        #pragma unroll
        for (int i = 0; i < 80; i++) {
            const int j = i >> 2;
            if ((i & 3) == 0) {
                float4 sa = s_se[j][lane8], sb = s_se[j][lane8 + 8];
                s0 = fpack(sa.x, sa.y); s1 = fpack(sa.z, sa.w);
                s2 = fpack(sb.x, sb.y); s3 = fpack(sb.z, sb.w);
            }
            const int p = i & 3;
            f2 a = fmul2(qv[p][0], s0);
            a = ffma2(qv[p][1], s1, a);
            a = ffma2(qv[p][2], s2, a);
            a = ffma2(qv[p][3], s3, a);
            float x, y; funpack(a, x, y);
            part[i & 7] = x + y;
            if ((i & 7) == 7) {
                float red = rscatter8(part, lane8);
                const int pp = lane8 & 3;
                const int jj = 2 * (i >> 3) + (lane8 >> 2);
                s_e[egbase + pp * EPOS + jj] = red + s_pb[jj];
            }
        }
    }
    __syncwarp();

    // 7/8 of CTAs need no clamping or masking at all (CTA-uniform branch).
    if (!clamp) {
        run_main<false>(n0, lane8, egbase, kb4, vb4, qv, kf, s_e, ob4);
    } else {
        run_main<true>(n0, lane8, egbase, kb4, vb4, qv, kf, s_e, ob4);
    }
}

extern "C" void kernel_launch(void* const* d_in, const int* in_sizes, int n_in,
                              void* d_out, int out_size)
{
    const float* q  = (const float*)d_in[0];
    const float* k  = (const float*)d_in[1];
    const float* v  = (const float*)d_in[2];
    const float* pb = (const float*)d_in[3];
    const float* se = (const float*)d_in[4];
    float* out = (float*)d_out;

    const int blocks = NB * NH * (NSEQ / POS_PER_CTA);   // 8192
    dsqg_attn_kernel<<<blocks, 256>>>(q, k, v, pb, se, out);
}